// round 10
// baseline (speedup 1.0000x reference)
#include <cuda_runtime.h>
#include <cstdint>

// VoxelHashTable: 2-level hash-grid trilinear interpolation.
// Inputs (metadata order):
//   d_in[0] query_pts (M,3) f32
//   d_in[1] feats0    (n0,32) f32
//   d_in[2] feats1    (n1,32) f32
//   d_in[3] h2v0      (2^20) i32
//   d_in[4] h2v1      (2^20) i32
// Output: (M, 64) f32  — [level0 32 | level1 32]
//
// Warp layout (1 warp = 4 queries = two pairs A, B):
//   half  = lane>>4        which query of the pair
//   level = (lane>>3)&1    resolution level this lane serves
//   s     = lane&7         channel chunk (floats 4s..4s+3)
// Prologue issues BOTH pairs' hash LDGs back-to-back. The gather loop is
// INTERLEAVED: every iteration issues one A-load and one B-load (independent),
// so the warp always has >=2 feature loads in flight — the kernel is L1
// wavefront-bound with L2-hit latency (~250cyc) to hide, and per-warp MLP is
// what converts occupancy into L1 throughput.
//
// __launch_bounds__(256, 6): 40-reg budget ((256,7) truncates to 32 and spills).

#define TSIZE_MASK ((1 << 20) - 1)

// PRIMES % 2^20 (exact):
#define PMX 455773
#define PMY 475301
#define PMZ 655287

__global__ __launch_bounds__(256, 6) void voxel_hash_kernel(
    const float* __restrict__ q,
    const float* __restrict__ f0,
    const float* __restrict__ f1,
    const int* __restrict__ h0,
    const int* __restrict__ h1,
    float* __restrict__ out,
    int M)
{
    const int wid  = (blockIdx.x * blockDim.x + threadIdx.x) >> 5;
    const int lane = threadIdx.x & 31;

    const int level = (lane >> 3) & 1;
    const int s     = lane & 7;
    const int half  = lane >> 4;

    const int base = wid * 4;
    int qA = base + half;
    int qB = base + 2 + half;
    const bool actA = qA < M;
    const bool actB = qB < M;
    if (qA >= M) qA = M - 1;
    if (qB >= M) qB = M - 1;

    const float res = level ? 0.24f : 0.12f;   // 0.24f == float32(0.12*2.0)
    const int*   __restrict__ hp = level ? h1 : h0;
    const float* __restrict__ fp = (level ? f1 : f0) + s * 4;
    const int src_base = lane & 0x18;          // (half<<4) | (level<<3)
    const int oxb = (lane >> 2) & 1;
    const int oyb = (lane >> 1) & 1;
    const int ozb = lane & 1;

    // ---- Prologue: both pairs' query points + hash lookups in flight ----
    const float qAx = __ldg(q + qA * 3 + 0);
    const float qAy = __ldg(q + qA * 3 + 1);
    const float qAz = __ldg(q + qA * 3 + 2);
    const float qBx = __ldg(q + qB * 3 + 0);
    const float qBy = __ldg(q + qB * 3 + 1);
    const float qBz = __ldg(q + qB * 3 + 2);

    const float sxA = __fdiv_rn(qAx, res);
    const float syA = __fdiv_rn(qAy, res);
    const float szA = __fdiv_rn(qAz, res);
    const float bxA = floorf(sxA), byA = floorf(syA), bzA = floorf(szA);
    const float fxA = sxA - bxA, fyA = syA - byA, fzA = szA - bzA;

    int vidxA;
    {
        const unsigned hv = ((unsigned)(((int)bxA + oxb) * PMX +
                                        ((int)byA + oyb) * PMY +
                                        ((int)bzA + ozb) * PMZ)) & TSIZE_MASK;
        vidxA = __ldg(hp + hv);
    }

    const float sxB = __fdiv_rn(qBx, res);
    const float syB = __fdiv_rn(qBy, res);
    const float szB = __fdiv_rn(qBz, res);
    const float bxB = floorf(sxB), byB = floorf(syB), bzB = floorf(szB);
    const float fxB = sxB - bxB, fyB = syB - byB, fzB = szB - bzB;

    int vidxB;
    {
        const unsigned hv = ((unsigned)(((int)bxB + oxb) * PMX +
                                        ((int)byB + oyb) * PMY +
                                        ((int)bzB + ozb) * PMZ)) & TSIZE_MASK;
        vidxB = __ldg(hp + hv);
    }

    const float gxA = 1.0f - fxA, gyA = 1.0f - fyA, gzA = 1.0f - fzA;
    const float gxB = 1.0f - fxB, gyB = 1.0f - fyB, gzB = 1.0f - fzB;

    float4 accA = make_float4(0.f, 0.f, 0.f, 0.f);
    float4 accB = make_float4(0.f, 0.f, 0.f, 0.f);

    // ---- Interleaved gather: 2 independent loads in flight per iteration ----
    #pragma unroll
    for (int t = 0; t < 8; ++t) {
        const int vA = __shfl_sync(0xFFFFFFFFu, vidxA, src_base + t);
        const int vB = __shfl_sync(0xFFFFFFFFu, vidxB, src_base + t);

        // ((wx*wy)*wz) multiply order matches reference prod(axis=2).
        const float wA = ((t & 4) ? fxA : gxA) *
                         ((t & 2) ? fyA : gyA) *
                         ((t & 1) ? fzA : gzA);
        const float wB = ((t & 4) ? fxB : gxB) *
                         ((t & 2) ? fyB : gyB) *
                         ((t & 1) ? fzB : gzB);

        if (vA >= 0) {
            const float4 f = __ldg((const float4*)(fp + (size_t)vA * 32));
            accA.x = fmaf(f.x, wA, accA.x);
            accA.y = fmaf(f.y, wA, accA.y);
            accA.z = fmaf(f.z, wA, accA.z);
            accA.w = fmaf(f.w, wA, accA.w);
        }
        if (vB >= 0) {
            const float4 f = __ldg((const float4*)(fp + (size_t)vB * 32));
            accB.x = fmaf(f.x, wB, accB.x);
            accB.y = fmaf(f.y, wB, accB.y);
            accB.z = fmaf(f.z, wB, accB.z);
            accB.w = fmaf(f.w, wB, accB.w);
        }
    }

    // Each lane writes its own (query, level, chunk): 512B coalesced per pair.
    if (actA) {
        *(float4*)(out + (size_t)qA * 64 + level * 32 + s * 4) = accA;
    }
    if (actB) {
        *(float4*)(out + (size_t)qB * 64 + level * 32 + s * 4) = accB;
    }
}

extern "C" void kernel_launch(void* const* d_in, const int* in_sizes, int n_in,
                              void* d_out, int out_size)
{
    const float* q  = (const float*)d_in[0];
    const float* f0 = (const float*)d_in[1];
    const float* f1 = (const float*)d_in[2];
    const int*   h0 = (const int*)d_in[3];
    const int*   h1 = (const int*)d_in[4];
    float* out = (float*)d_out;

    const int M = in_sizes[0] / 3;
    const int warps = (M + 3) / 4;          // 4 queries per warp

    const int warps_per_block = 8;
    const int blocks = (warps + warps_per_block - 1) / warps_per_block;
    voxel_hash_kernel<<<blocks, warps_per_block * 32>>>(q, f0, f1, h0, h1, out, M);
}